// round 15
// baseline (speedup 1.0000x reference)
#include <cuda_runtime.h>
#include <cuda_bf16.h>
#include <cuda_fp16.h>
#include <cstdint>
#define B_ 2
#define S_ 2048
#define D_ 1024
#define H_ 16
#define NACT (B_*S_*D_)

__device__ float g_V[NACT];                         // fp32 V projection
__device__ __half g_Ah[3*NACT], g_Al[3*NACT];       // act hi/lo fp16 (slot0 reused for ctx)
__device__ __half g_Wh[4*D_*D_];                    // weights single fp16 plane
__device__ __half g_Qh[NACT], g_Ql[NACT];           // attn Q planes (scaled)
__device__ __half g_Kh[NACT];                       // attn K plane
__device__ __half g_Vt[NACT];                       // V^T fp16 [b][h][d][s]
__device__ uint32_t g_mb[S_*S_/32];                 // mask bitplane

__device__ __forceinline__ uint32_t smem_u32(const void* p){
    uint32_t a; asm("{ .reg .u64 t; cvta.to.shared.u64 t, %1; cvt.u32.u64 %0, t; }":"=r"(a):"l"(p)); return a;
}
__device__ __forceinline__ void ldsm4(uint32_t* r, uint32_t a){
    asm volatile("ldmatrix.sync.aligned.m8n8.x4.shared.b16 {%0,%1,%2,%3}, [%4];"
        :"=r"(r[0]),"=r"(r[1]),"=r"(r[2]),"=r"(r[3]):"r"(a));
}
__device__ __forceinline__ void mmaf16(float* c, const uint32_t* a, uint32_t b0, uint32_t b1){
    asm("mma.sync.aligned.m16n8k16.row.col.f32.f16.f16.f32 "
        "{%0,%1,%2,%3}, {%4,%5,%6,%7}, {%8,%9}, {%0,%1,%2,%3};"
        :"+f"(c[0]),"+f"(c[1]),"+f"(c[2]),"+f"(c[3])
        :"r"(a[0]),"r"(a[1]),"r"(a[2]),"r"(a[3]),"r"(b0),"r"(b1));
}
__device__ __forceinline__ void cpa16(uint32_t d, const void* s){
    asm volatile("cp.async.cg.shared.global [%0], [%1], 16;"::"r"(d),"l"(s):"memory");
}
__device__ __forceinline__ uint32_t pkh2(float a, float b){
    __half2 h = __floats2half2_rn(a, b);
    return *reinterpret_cast<uint32_t*>(&h);
}
__device__ __forceinline__ float hlo(float v){
    return v - __half2float(__float2half_rn(v));
}
__device__ __forceinline__ float ex2(float x){
    float r; asm("ex2.approx.ftz.f32 %0, %1;":"=f"(r):"f"(x)); return r;
}

// ---------------- mask -> bitplane ----------------
__global__ void __launch_bounds__(256)
maskbits_kernel(const int* __restrict__ mask, uint32_t* __restrict__ bits)
{
    int i = blockIdx.x * 256 + threadIdx.x;
    uint32_t b = __ballot_sync(0xffffffffu, mask[i] != 0);
    if ((threadIdx.x & 31) == 0) bits[i >> 5] = b;
}

// ---------------- z-batched fp32 -> fp16 hi/lo ----------------
__global__ void __launch_bounds__(256)
cvt3_kernel(const float* __restrict__ i0, const float* __restrict__ i1,
            const float* __restrict__ i2, __half* __restrict__ hi,
            __half* __restrict__ lo, int slot_u2)
{
    int z = blockIdx.y;
    const float* in = (z == 0) ? i0 : (z == 1) ? i1 : i2;
    int i = blockIdx.x * 256 + threadIdx.x;
    float4 v = ((const float4*)in)[i];
    float a[4] = {v.x, v.y, v.z, v.w};
    unsigned short h[4], l[4];
    #pragma unroll
    for (int j = 0; j < 4; j++) {
        __half hb = __float2half_rn(a[j]);
        h[j] = __half_as_ushort(hb);
        l[j] = __half_as_ushort(__float2half_rn(a[j] - __half2float(hb)));
    }
    size_t o = (size_t)z * slot_u2 + i;
    ((uint2*)hi)[o] = make_uint2(h[0]|((uint32_t)h[1]<<16), h[2]|((uint32_t)h[3]<<16));
    ((uint2*)lo)[o] = make_uint2(l[0]|((uint32_t)l[1]<<16), l[2]|((uint32_t)l[3]<<16));
}
__global__ void __launch_bounds__(256)
cvtw_kernel(const float* __restrict__ i0, const float* __restrict__ i1,
            const float* __restrict__ i2, const float* __restrict__ i3,
            __half* __restrict__ hi, int slot_u2)
{
    int z = blockIdx.y;
    const float* in = (z == 0) ? i0 : (z == 1) ? i1 : (z == 2) ? i2 : i3;
    int i = blockIdx.x * 256 + threadIdx.x;
    float4 v = ((const float4*)in)[i];
    unsigned short h[4] = {
        __half_as_ushort(__float2half_rn(v.x)), __half_as_ushort(__float2half_rn(v.y)),
        __half_as_ushort(__float2half_rn(v.z)), __half_as_ushort(__float2half_rn(v.w))};
    ((uint2*)hi)[(size_t)z * slot_u2 + i] =
        make_uint2(h[0]|((uint32_t)h[1]<<16), h[2]|((uint32_t)h[3]<<16));
}
// V[b][s][h*64+d] -> Vt[b][h][d][s] fp16
__global__ void __launch_bounds__(256)
cvtT_kernel(const float* __restrict__ V, __half* __restrict__ oh)
{
    __shared__ float tile[32][33];
    const int s0 = blockIdx.x*32, d0 = blockIdx.y*32, b = blockIdx.z;
    const int tx = threadIdx.x & 31, ty = threadIdx.x >> 5;
    #pragma unroll
    for (int i = 0; i < 4; i++)
        tile[ty+8*i][tx] = V[((size_t)(b*S_+s0+ty+8*i))*D_ + d0+tx];
    __syncthreads();
    const int hh = d0 >> 6, dl = d0 & 63;
    #pragma unroll
    for (int i = 0; i < 4; i++) {
        int dr = ty + 8*i;
        size_t a = ((size_t)((b*H_+hh)*64 + dl + dr))*S_ + s0 + tx;
        oh[a] = __float2half(tile[tx][dr]);
    }
}

// ---------------------------------------------------------------------------
// fp16 2-term GEMM: CTA tile 128x256, 8 warps (2Mx4N, warp tile 64x64),
// BK=32, 3-stage cp.async ring, 1 CTA/SM (255-reg budget).
// Stage: Ah(128x80) + Al(128x80) + W(256x80) = 40960 B.
// ---------------------------------------------------------------------------
static constexpr int APL  = 128 * 80;      // 10240 (per A plane)
static constexpr int WOF  = 2 * APL;       // 20480 (W plane offset)
static constexpr int STGB = WOF + 256*80;  // 40960 per stage
static constexpr int GSM  = 3 * STGB;      // 122880

#define GISSUE(c, s) do { \
    uint32_t d = sb + (s) * STGB; int go = (c) * 64; \
    uint32_t da = d + (t >> 1) * 80 + (t & 1) * 32; \
    cpa16(da,            pAh + go); cpa16(da + 16,            pAh + go + 16); \
    cpa16(da + APL,      pAl + go); cpa16(da + APL + 16,      pAl + go + 16); \
    uint32_t dw = d + WOF + t * 80; \
    cpa16(dw,      pW + go);      cpa16(dw + 16, pW + go + 16); \
    cpa16(dw + 32, pW + go + 32); cpa16(dw + 48, pW + go + 48); \
    asm volatile("cp.async.commit_group;" ::: "memory"); \
} while (0)

#define GEMM_CORE(gAh, gAl, gW, acc) do { \
    const char* pAh = (const char*)((gAh) + (size_t)(bm + (t >> 1)) * D_) + (t & 1) * 32; \
    const char* pAl = (const char*)((gAl) + (size_t)(bm + (t >> 1)) * D_) + (t & 1) * 32; \
    const char* pW  = (const char*)((gW)  + (size_t)(bn + t) * D_); \
    const int NCH = D_ / 32; \
    GISSUE(0, 0); GISSUE(1, 1); \
    for (int c = 0; c < NCH; c++) { \
        const int s = c % 3; \
        if (c + 2 < NCH) { GISSUE(c + 2, (c + 2) % 3); \
            asm volatile("cp.async.wait_group 2;" ::: "memory"); } \
        else if (c + 1 < NCH) { asm volatile("cp.async.wait_group 1;" ::: "memory"); } \
        else { asm volatile("cp.async.wait_group 0;" ::: "memory"); } \
        __syncthreads(); \
        const uint32_t base = sb + s * STGB; \
        const int arow = mw + (lane & 15); \
        const int brow = nw + (lane & 7) + ((lane >> 4) << 3); \
        _Pragma("unroll") \
        for (int ks = 0; ks < 2; ks++) { \
            const int acol = ks * 32 + ((lane >> 4) << 4); \
            const int bcol = ks * 32 + (((lane >> 3) & 1) << 4); \
            uint32_t ah[4][4], al[4][4]; \
            _Pragma("unroll") \
            for (int mf = 0; mf < 4; mf++) { \
                uint32_t ad = base + (arow + mf * 16) * 80 + acol; \
                ldsm4(ah[mf], ad); ldsm4(al[mf], ad + APL); \
            } \
            _Pragma("unroll") \
            for (int nf = 0; nf < 4; nf++) { \
                uint32_t bd = base + WOF + (brow + nf * 16) * 80 + bcol; \
                uint32_t bh[4]; \
                ldsm4(bh, bd); \
                _Pragma("unroll") \
                for (int mf = 0; mf < 4; mf++) { \
                    mmaf16(acc[mf][2*nf],   ah[mf], bh[0], bh[1]); \
                    mmaf16(acc[mf][2*nf+1], ah[mf], bh[2], bh[3]); \
                } \
                _Pragma("unroll") \
                for (int mf = 0; mf < 4; mf++) { \
                    mmaf16(acc[mf][2*nf],   al[mf], bh[0], bh[1]); \
                    mmaf16(acc[mf][2*nf+1], al[mf], bh[2], bh[3]); \
                } \
            } \
        } \
        __syncthreads(); \
    } \
} while (0)

// z-batched QKV projection: z=0 -> Q fp16 hi/lo (scaled), z=1 -> K fp16, z=2 -> V fp32
__global__ void __launch_bounds__(256, 1)
gemm_qkv(const __half* __restrict__ Ah3, const __half* __restrict__ Al3,
         const __half* __restrict__ Wh4,
         const float* __restrict__ bq, const float* __restrict__ bk,
         const float* __restrict__ bv, float* __restrict__ Vout,
         __half* __restrict__ Qh, __half* __restrict__ Ql,
         __half* __restrict__ Kh, float qsc)
{
    extern __shared__ __align__(128) char sm[];
    const uint32_t sb = smem_u32(sm);
    const int t = threadIdx.x, lane = t & 31, w = t >> 5;
    const int bm = blockIdx.y * 128, bn = blockIdx.x * 256;
    const int mw = (w >> 2) * 64, nw = (w & 3) * 64;
    const int z = blockIdx.z;
    const __half* Ah = Ah3 + (size_t)z * NACT;
    const __half* Al = Al3 + (size_t)z * NACT;
    const __half* W  = Wh4 + (size_t)z * D_ * D_;
    const float* bias = (z == 0) ? bq : (z == 1) ? bk : bv;

    float acc[4][8][4] = {};
    GEMM_CORE(Ah, Al, W, acc);

    const float osc = (z == 0) ? qsc : 1.0f;
    #pragma unroll
    for (int mf = 0; mf < 4; mf++) {
        const int r0 = bm + mw + mf * 16 + (lane >> 2);
        #pragma unroll
        for (int nj = 0; nj < 8; nj++) {
            const int col = bn + nw + nj * 8 + (lane & 3) * 2;
            float2 bv2 = *(const float2*)&bias[col];
            float* c = acc[mf][nj];
            float v0 = (c[0] + bv2.x) * osc, v1 = (c[1] + bv2.y) * osc;
            float v2 = (c[2] + bv2.x) * osc, v3 = (c[3] + bv2.y) * osc;
            if (z == 2) {
                *(float2*)&Vout[(size_t)r0 * D_ + col] = make_float2(v0, v1);
                *(float2*)&Vout[(size_t)(r0 + 8) * D_ + col] = make_float2(v2, v3);
            } else if (z == 1) {
                *(uint32_t*)&Kh[(size_t)r0 * D_ + col]       = pkh2(v0, v1);
                *(uint32_t*)&Kh[(size_t)(r0 + 8) * D_ + col] = pkh2(v2, v3);
            } else {
                *(uint32_t*)&Qh[(size_t)r0 * D_ + col]       = pkh2(v0, v1);
                *(uint32_t*)&Ql[(size_t)r0 * D_ + col]       = pkh2(hlo(v0), hlo(v1));
                *(uint32_t*)&Qh[(size_t)(r0 + 8) * D_ + col] = pkh2(v2, v3);
                *(uint32_t*)&Ql[(size_t)(r0 + 8) * D_ + col] = pkh2(hlo(v2), hlo(v3));
            }
        }
    }
}

// O projection: fp32 out
__global__ void __launch_bounds__(256, 1)
gemm_o(const __half* __restrict__ Ah, const __half* __restrict__ Al,
       const __half* __restrict__ W, const float* __restrict__ bias,
       float* __restrict__ outf)
{
    extern __shared__ __align__(128) char sm[];
    const uint32_t sb = smem_u32(sm);
    const int t = threadIdx.x, lane = t & 31, w = t >> 5;
    const int bm = blockIdx.y * 128, bn = blockIdx.x * 256;
    const int mw = (w >> 2) * 64, nw = (w & 3) * 64;

    float acc[4][8][4] = {};
    GEMM_CORE(Ah, Al, W, acc);

    #pragma unroll
    for (int mf = 0; mf < 4; mf++) {
        const int r0 = bm + mw + mf * 16 + (lane >> 2);
        #pragma unroll
        for (int nj = 0; nj < 8; nj++) {
            const int col = bn + nw + nj * 8 + (lane & 3) * 2;
            float2 bv2 = *(const float2*)&bias[col];
            float* c = acc[mf][nj];
            *(float2*)&outf[(size_t)r0 * D_ + col] = make_float2(c[0] + bv2.x, c[1] + bv2.y);
            *(float2*)&outf[(size_t)(r0 + 8) * D_ + col] = make_float2(c[2] + bv2.x, c[3] + bv2.y);
        }
    }
}

// ---------------------------------------------------------------------------
// fp16 flash attention (round-14, passing): QK^T 2-term, PV 1-term,
// exp2 softmax, bitmask, 3-stage K/V ring, fp16 hi/lo ctx output.
// ---------------------------------------------------------------------------
static constexpr int KST   = 144;
static constexpr int KPL   = 64 * KST;
static constexpr int ASTG2 = 2 * KPL;
static constexpr int ASM   = 3 * ASTG2;
static constexpr int QLO   = 128 * KST;

__global__ void __launch_bounds__(128, 2)
attn_mma(const __half* __restrict__ Qh, const __half* __restrict__ Ql,
         const __half* __restrict__ Kh, const __half* __restrict__ Vt,
         const uint32_t* __restrict__ mb,
         __half* __restrict__ ctxh, __half* __restrict__ ctxl)
{
    extern __shared__ __align__(128) char sm[];
    const uint32_t sb = smem_u32(sm);
    const int t = threadIdx.x, lane = t & 31, w = t >> 5;
    const int b = blockIdx.z, h = blockIdx.y, q0 = blockIdx.x * 128;
    const int g = lane >> 2, qt = lane & 3;

    {
        const char* ph = (const char*)(Qh + ((size_t)(b*S_ + q0 + t))*D_ + h*64);
        const char* pl = (const char*)(Ql + ((size_t)(b*S_ + q0 + t))*D_ + h*64);
        uint32_t d = sb + t * KST;
        #pragma unroll
        for (int i = 0; i < 8; i++) { cpa16(d + i*16, ph + i*16); cpa16(d + QLO + i*16, pl + i*16); }
        asm volatile("cp.async.commit_group;" ::: "memory");
        asm volatile("cp.async.wait_group 0;" ::: "memory");
    }
    __syncthreads();
    uint32_t qfh[2][4][4], qfl[2][4][4];
    #pragma unroll
    for (int mi = 0; mi < 2; mi++)
        #pragma unroll
        for (int kc = 0; kc < 4; kc++) {
            uint32_t a = sb + (w*32 + mi*16 + (lane & 15)) * KST + kc*32 + ((lane >> 4) << 4);
            ldsm4(qfh[mi][kc], a);
            ldsm4(qfl[mi][kc], a + QLO);
        }
    __syncthreads();

    float o[2][8][4] = {};
    float m_i[2][2], l_i[2][2];
    #pragma unroll
    for (int mi = 0; mi < 2; mi++) { m_i[mi][0]=m_i[mi][1]=-1e30f; l_i[mi][0]=l_i[mi][1]=0.f; }

    const int krow = t >> 1, khalf = (t & 1) * 64;
    #define AISSUE(c, s) do { \
        uint32_t dd = sb + (s)*ASTG2 + krow*KST + khalf; \
        const char* pkh = (const char*)(Kh + ((size_t)(b*S_ + (c)*64 + krow))*D_ + h*64) + khalf; \
        const char* pvh = (const char*)(Vt + ((size_t)((b*H_+h)*64 + krow))*S_ + (c)*64) + khalf; \
        _Pragma("unroll") for (int i = 0; i < 4; i++) { \
            cpa16(dd + i*16,       pkh + i*16); \
            cpa16(dd + KPL + i*16, pvh + i*16); } \
        asm volatile("cp.async.commit_group;" ::: "memory"); \
    } while (0)

    const int NT = S_ / 64;
    AISSUE(0, 0); AISSUE(1, 1);
    for (int c = 0; c < NT; c++) {
        const int s = c % 3;
        if (c + 2 < NT) { AISSUE(c + 2, (c + 2) % 3);
            asm volatile("cp.async.wait_group 2;" ::: "memory"); }
        else if (c + 1 < NT) { asm volatile("cp.async.wait_group 1;" ::: "memory"); }
        else { asm volatile("cp.async.wait_group 0;" ::: "memory"); }
        __syncthreads();
        const uint32_t base = sb + s * ASTG2;
        const int brow = (lane & 7) + ((lane >> 4) << 3);
        const int bcsel = ((lane >> 3) & 1) << 4;

        uint2 mwa[2], mwb[2];
        #pragma unroll
        for (int mi = 0; mi < 2; mi++) {
            const uint32_t* mp = mb + (size_t)(q0 + w*32 + mi*16 + g) * (S_/32) + c*2;
            mwa[mi] = *(const uint2*)mp;
            mwb[mi] = *(const uint2*)(mp + 8 * (S_/32));
        }

        float sacc[2][8][4] = {};
        #pragma unroll
        for (int kc = 0; kc < 4; kc++)
            #pragma unroll
            for (int np = 0; np < 4; np++) {
                uint32_t ad = base + (np*16 + brow) * KST + kc*32 + bcsel;
                uint32_t kf[4];
                ldsm4(kf, ad);
                mmaf16(sacc[0][2*np],   qfh[0][kc], kf[0], kf[1]);
                mmaf16(sacc[0][2*np+1], qfh[0][kc], kf[2], kf[3]);
                mmaf16(sacc[1][2*np],   qfh[1][kc], kf[0], kf[1]);
                mmaf16(sacc[1][2*np+1], qfh[1][kc], kf[2], kf[3]);
                mmaf16(sacc[0][2*np],   qfl[0][kc], kf[0], kf[1]);
                mmaf16(sacc[0][2*np+1], qfl[0][kc], kf[2], kf[3]);
                mmaf16(sacc[1][2*np],   qfl[1][kc], kf[0], kf[1]);
                mmaf16(sacc[1][2*np+1], qfl[1][kc], kf[2], kf[3]);
            }

        #pragma unroll
        for (int mi = 0; mi < 2; mi++) {
            uint32_t allm = mwa[mi].x & mwa[mi].y & mwb[mi].x & mwb[mi].y;
            if (allm != 0xFFFFFFFFu) {
                #pragma unroll
                for (int nf = 0; nf < 8; nf++) {
                    uint32_t w0 = (nf < 4) ? mwa[mi].x : mwa[mi].y;
                    uint32_t w1 = (nf < 4) ? mwb[mi].x : mwb[mi].y;
                    int sh = qt*2 + (nf & 3)*8;
                    if (!((w0 >> sh) & 1))     sacc[mi][nf][0] = -1e9f;
                    if (!((w0 >> (sh+1)) & 1)) sacc[mi][nf][1] = -1e9f;
                    if (!((w1 >> sh) & 1))     sacc[mi][nf][2] = -1e9f;
                    if (!((w1 >> (sh+1)) & 1)) sacc[mi][nf][3] = -1e9f;
                }
            }
            float mx0 = -1e30f, mx1 = -1e30f;
            #pragma unroll
            for (int nf = 0; nf < 8; nf++) {
                mx0 = fmaxf(mx0, fmaxf(sacc[mi][nf][0], sacc[mi][nf][1]));
                mx1 = fmaxf(mx1, fmaxf(sacc[mi][nf][2], sacc[mi][nf][3]));
            }
            mx0 = fmaxf(mx0, __shfl_xor_sync(0xffffffffu, mx0, 1));
            mx0 = fmaxf(mx0, __shfl_xor_sync(0xffffffffu, mx0, 2));
            mx1 = fmaxf(mx1, __shfl_xor_sync(0xffffffffu, mx1, 1));
            mx1 = fmaxf(mx1, __shfl_xor_sync(0xffffffffu, mx1, 2));
            float mn0 = fmaxf(m_i[mi][0], mx0), mn1 = fmaxf(m_i[mi][1], mx1);
            float al0 = ex2(m_i[mi][0] - mn0), al1 = ex2(m_i[mi][1] - mn1);
            float s0 = 0.f, s1 = 0.f;
            #pragma unroll
            for (int nf = 0; nf < 8; nf++) {
                sacc[mi][nf][0] = ex2(sacc[mi][nf][0] - mn0);
                sacc[mi][nf][1] = ex2(sacc[mi][nf][1] - mn0);
                sacc[mi][nf][2] = ex2(sacc[mi][nf][2] - mn1);
                sacc[mi][nf][3] = ex2(sacc[mi][nf][3] - mn1);
                s0 += sacc[mi][nf][0] + sacc[mi][nf][1];
                s1 += sacc[mi][nf][2] + sacc[mi][nf][3];
            }
            s0 += __shfl_xor_sync(0xffffffffu, s0, 1);
            s0 += __shfl_xor_sync(0xffffffffu, s0, 2);
            s1 += __shfl_xor_sync(0xffffffffu, s1, 1);
            s1 += __shfl_xor_sync(0xffffffffu, s1, 2);
            l_i[mi][0] = l_i[mi][0]*al0 + s0; m_i[mi][0] = mn0;
            l_i[mi][1] = l_i[mi][1]*al1 + s1; m_i[mi][1] = mn1;
            #pragma unroll
            for (int nf = 0; nf < 8; nf++) {
                o[mi][nf][0] *= al0; o[mi][nf][1] *= al0;
                o[mi][nf][2] *= al1; o[mi][nf][3] *= al1;
            }
        }

        #pragma unroll
        for (int kc = 0; kc < 4; kc++) {
            uint32_t ph[2][4];
            #pragma unroll
            for (int mi = 0; mi < 2; mi++) {
                float* c0 = sacc[mi][2*kc];
                float* c1 = sacc[mi][2*kc+1];
                ph[mi][0] = pkh2(c0[0], c0[1]); ph[mi][1] = pkh2(c0[2], c0[3]);
                ph[mi][2] = pkh2(c1[0], c1[1]); ph[mi][3] = pkh2(c1[2], c1[3]);
            }
            #pragma unroll
            for (int np = 0; np < 4; np++) {
                uint32_t vd = base + KPL + (np*16 + brow) * KST + kc*32 + bcsel;
                uint32_t vh[4];
                ldsm4(vh, vd);
                mmaf16(o[0][2*np],   ph[0], vh[0], vh[1]);
                mmaf16(o[0][2*np+1], ph[0], vh[2], vh[3]);
                mmaf16(o[1][2*np],   ph[1], vh[0], vh[1]);
                mmaf16(o[1][2*np+1], ph[1], vh[2], vh[3]);
            }
        }
        __syncthreads();
    }
    #undef AISSUE

    #pragma unroll
    for (int mi = 0; mi < 2; mi++) {
        const int r0 = q0 + w*32 + mi*16 + g;
        const float i0 = 1.f / l_i[mi][0], i1 = 1.f / l_i[mi][1];
        #pragma unroll
        for (int nf = 0; nf < 8; nf++) {
            const int col = h*64 + nf*8 + qt*2;
            float v0 = o[mi][nf][0]*i0, v1 = o[mi][nf][1]*i0;
            float v2 = o[mi][nf][2]*i1, v3 = o[mi][nf][3]*i1;
            *(uint32_t*)&ctxh[(size_t)(b*S_ + r0)*D_ + col]     = pkh2(v0, v1);
            *(uint32_t*)&ctxl[(size_t)(b*S_ + r0)*D_ + col]     = pkh2(hlo(v0), hlo(v1));
            *(uint32_t*)&ctxh[(size_t)(b*S_ + r0 + 8)*D_ + col] = pkh2(v2, v3);
            *(uint32_t*)&ctxl[(size_t)(b*S_ + r0 + 8)*D_ + col] = pkh2(hlo(v2), hlo(v3));
        }
    }
}

// ---------------------------------------------------------------------------
extern "C" void kernel_launch(void* const* d_in, const int* in_sizes, int n_in,
                              void* d_out, int out_size)
{
    const float* q  = (const float*)d_in[0];
    const float* k  = (const float*)d_in[1];
    const float* v  = (const float*)d_in[2];
    const int* mask = (const int*)  d_in[3];
    const float* Wq = (const float*)d_in[4];  const float* bq = (const float*)d_in[5];
    const float* Wk = (const float*)d_in[6];  const float* bk = (const float*)d_in[7];
    const float* Wv = (const float*)d_in[8];  const float* bv = (const float*)d_in[9];
    const float* Wo = (const float*)d_in[10]; const float* bo = (const float*)d_in[11];
    float* out = (float*)d_out;

    float *Vp;
    __half *Ahp, *Alp, *Whp, *Qhp, *Qlp, *Khp, *Vtp;
    uint32_t* mbp;
    cudaGetSymbolAddress((void**)&Vp, g_V);
    cudaGetSymbolAddress((void**)&Ahp, g_Ah); cudaGetSymbolAddress((void**)&Alp, g_Al);
    cudaGetSymbolAddress((void**)&Whp, g_Wh);
    cudaGetSymbolAddress((void**)&Qhp, g_Qh); cudaGetSymbolAddress((void**)&Qlp, g_Ql);
    cudaGetSymbolAddress((void**)&Khp, g_Kh);
    cudaGetSymbolAddress((void**)&Vtp, g_Vt);
    cudaGetSymbolAddress((void**)&mbp, g_mb);

    const int MA4 = NACT / 4 / 256;
    const int MW4 = (D_ * D_) / 4 / 256;
    const float QSC = 0.125f * 1.44269504088896f;

    cudaFuncSetAttribute(gemm_qkv, cudaFuncAttributeMaxDynamicSharedMemorySize, GSM);
    cudaFuncSetAttribute(gemm_o,   cudaFuncAttributeMaxDynamicSharedMemorySize, GSM);
    cudaFuncSetAttribute(attn_mma, cudaFuncAttributeMaxDynamicSharedMemorySize, ASM);

    maskbits_kernel<<<(S_*S_)/256, 256>>>(mask, mbp);
    cvt3_kernel<<<dim3(MA4, 3), 256>>>(q, k, v, Ahp, Alp, NACT / 4);
    cvtw_kernel<<<dim3(MW4, 4), 256>>>(Wq, Wk, Wv, Wo, Whp, (D_ * D_) / 4);

    gemm_qkv<<<dim3(D_/256, (B_*S_)/128, 3), 256, GSM>>>(
        Ahp, Alp, Whp, bq, bk, bv, Vp, Qhp, Qlp, Khp, QSC);

    cvtT_kernel<<<dim3(S_/32, D_/32, B_), 256>>>(Vp, Vtp);

    attn_mma<<<dim3(S_/128, H_, B_), 128, ASM>>>(Qhp, Qlp, Khp, Vtp, mbp, Ahp, Alp);

    gemm_o<<<dim3(D_/256, (B_*S_)/128), 256, GSM>>>(
        Ahp, Alp, Whp + (size_t)3*D_*D_, bo, out);
}

// round 16
// speedup vs baseline: 1.2170x; 1.2170x over previous
#include <cuda_runtime.h>
#include <cuda_bf16.h>
#include <cuda_fp16.h>
#include <cstdint>
#define B_ 2
#define S_ 2048
#define D_ 1024
#define H_ 16
#define NACT (B_*S_*D_)

__device__ float g_V[NACT];                         // fp32 V projection
__device__ __half g_Ah[3*NACT], g_Al[NACT];         // act fp16: 3 hi slots (q,k,v); 1 lo slot (ctx)
__device__ __half g_Wh[4*D_*D_];                    // weights single fp16 plane
__device__ __half g_Qh[NACT], g_Ql[NACT];           // attn Q planes (scaled)
__device__ __half g_Kh[NACT];                       // attn K plane
__device__ __half g_Vt[NACT];                       // V^T fp16 [b][h][d][s]
__device__ uint32_t g_mb[S_*S_/32];                 // mask bitplane

__device__ __forceinline__ uint32_t smem_u32(const void* p){
    uint32_t a; asm("{ .reg .u64 t; cvta.to.shared.u64 t, %1; cvt.u32.u64 %0, t; }":"=r"(a):"l"(p)); return a;
}
__device__ __forceinline__ void ldsm4(uint32_t* r, uint32_t a){
    asm volatile("ldmatrix.sync.aligned.m8n8.x4.shared.b16 {%0,%1,%2,%3}, [%4];"
        :"=r"(r[0]),"=r"(r[1]),"=r"(r[2]),"=r"(r[3]):"r"(a));
}
__device__ __forceinline__ void mmaf16(float* c, const uint32_t* a, uint32_t b0, uint32_t b1){
    asm("mma.sync.aligned.m16n8k16.row.col.f32.f16.f16.f32 "
        "{%0,%1,%2,%3}, {%4,%5,%6,%7}, {%8,%9}, {%0,%1,%2,%3};"
        :"+f"(c[0]),"+f"(c[1]),"+f"(c[2]),"+f"(c[3])
        :"r"(a[0]),"r"(a[1]),"r"(a[2]),"r"(a[3]),"r"(b0),"r"(b1));
}
__device__ __forceinline__ void cpa16(uint32_t d, const void* s){
    asm volatile("cp.async.cg.shared.global [%0], [%1], 16;"::"r"(d),"l"(s):"memory");
}
__device__ __forceinline__ uint32_t pkh2(float a, float b){
    __half2 h = __floats2half2_rn(a, b);
    return *reinterpret_cast<uint32_t*>(&h);
}
__device__ __forceinline__ float hlo(float v){
    return v - __half2float(__float2half_rn(v));
}
__device__ __forceinline__ float ex2(float x){
    float r; asm("ex2.approx.ftz.f32 %0, %1;":"=f"(r):"f"(x)); return r;
}

// ---------------- mask -> bitplane ----------------
__global__ void __launch_bounds__(256)
maskbits_kernel(const int* __restrict__ mask, uint32_t* __restrict__ bits)
{
    int i = blockIdx.x * 256 + threadIdx.x;
    uint32_t b = __ballot_sync(0xffffffffu, mask[i] != 0);
    if ((threadIdx.x & 31) == 0) bits[i >> 5] = b;
}

// ---------------- z-batched fp32 -> fp16 single plane ----------------
__global__ void __launch_bounds__(256)
cvt3h_kernel(const float* __restrict__ i0, const float* __restrict__ i1,
             const float* __restrict__ i2, __half* __restrict__ hi, int slot_u2)
{
    int z = blockIdx.y;
    const float* in = (z == 0) ? i0 : (z == 1) ? i1 : i2;
    int i = blockIdx.x * 256 + threadIdx.x;
    float4 v = ((const float4*)in)[i];
    unsigned short h[4] = {
        __half_as_ushort(__float2half_rn(v.x)), __half_as_ushort(__float2half_rn(v.y)),
        __half_as_ushort(__float2half_rn(v.z)), __half_as_ushort(__float2half_rn(v.w))};
    ((uint2*)hi)[(size_t)z * slot_u2 + i] =
        make_uint2(h[0]|((uint32_t)h[1]<<16), h[2]|((uint32_t)h[3]<<16));
}
__global__ void __launch_bounds__(256)
cvtw_kernel(const float* __restrict__ i0, const float* __restrict__ i1,
            const float* __restrict__ i2, const float* __restrict__ i3,
            __half* __restrict__ hi, int slot_u2)
{
    int z = blockIdx.y;
    const float* in = (z == 0) ? i0 : (z == 1) ? i1 : (z == 2) ? i2 : i3;
    int i = blockIdx.x * 256 + threadIdx.x;
    float4 v = ((const float4*)in)[i];
    unsigned short h[4] = {
        __half_as_ushort(__float2half_rn(v.x)), __half_as_ushort(__float2half_rn(v.y)),
        __half_as_ushort(__float2half_rn(v.z)), __half_as_ushort(__float2half_rn(v.w))};
    ((uint2*)hi)[(size_t)z * slot_u2 + i] =
        make_uint2(h[0]|((uint32_t)h[1]<<16), h[2]|((uint32_t)h[3]<<16));
}
// V[b][s][h*64+d] -> Vt[b][h][d][s] fp16
__global__ void __launch_bounds__(256)
cvtT_kernel(const float* __restrict__ V, __half* __restrict__ oh)
{
    __shared__ float tile[32][33];
    const int s0 = blockIdx.x*32, d0 = blockIdx.y*32, b = blockIdx.z;
    const int tx = threadIdx.x & 31, ty = threadIdx.x >> 5;
    #pragma unroll
    for (int i = 0; i < 4; i++)
        tile[ty+8*i][tx] = V[((size_t)(b*S_+s0+ty+8*i))*D_ + d0+tx];
    __syncthreads();
    const int hh = d0 >> 6, dl = d0 & 63;
    #pragma unroll
    for (int i = 0; i < 4; i++) {
        int dr = ty + 8*i;
        size_t a = ((size_t)((b*H_+hh)*64 + dl + dr))*S_ + s0 + tx;
        oh[a] = __float2half(tile[tx][dr]);
    }
}

// ---------------------------------------------------------------------------
// GEMM cores: 128x128 CTA tile, 8 warps (4Mx2N, warp 32x64), BK=32,
// 3-stage cp.async ring. 1-term (A,W) and 2-term (Ah,Al,W) variants.
// ---------------------------------------------------------------------------
static constexpr int PLN   = 128 * 80;     // 10240 B per plane
static constexpr int STG1  = 2 * PLN;      // 20480 (1-term stage)
static constexpr int STG2  = 3 * PLN;      // 30720 (2-term stage)
static constexpr int GSM1  = 3 * STG1;     // 61440
static constexpr int GSM2  = 3 * STG2;     // 92160

#define G1ISSUE(c, s) do { \
    uint32_t d = dst0 + (s) * STG1; int go = (c) * 64; \
    cpa16(d,       pA + go); cpa16(d + 16,       pA + go + 16); \
    cpa16(d + PLN, pW + go); cpa16(d + PLN + 16, pW + go + 16); \
    asm volatile("cp.async.commit_group;" ::: "memory"); \
} while (0)

#define GEMM1_CORE(gA, gW, acc) do { \
    const int crow = t >> 1, coff = (t & 1) * 32; \
    const char* pA = (const char*)((gA) + (size_t)(bm + crow) * D_) + coff; \
    const char* pW = (const char*)((gW) + (size_t)(bn + crow) * D_) + coff; \
    const uint32_t dst0 = sb + crow * 80 + coff; \
    const int NCH = D_ / 32; \
    G1ISSUE(0, 0); G1ISSUE(1, 1); \
    for (int c = 0; c < NCH; c++) { \
        const int s = c % 3; \
        if (c + 2 < NCH) { G1ISSUE(c + 2, (c + 2) % 3); \
            asm volatile("cp.async.wait_group 2;" ::: "memory"); } \
        else if (c + 1 < NCH) { asm volatile("cp.async.wait_group 1;" ::: "memory"); } \
        else { asm volatile("cp.async.wait_group 0;" ::: "memory"); } \
        __syncthreads(); \
        const uint32_t base = sb + s * STG1; \
        const int arow = mw + (lane & 15); \
        const int brow = nw + (lane & 7) + ((lane >> 4) << 3); \
        _Pragma("unroll") \
        for (int ks = 0; ks < 2; ks++) { \
            const int acol = ks * 32 + ((lane >> 4) << 4); \
            const int bcol = ks * 32 + (((lane >> 3) & 1) << 4); \
            uint32_t ah[2][4]; \
            _Pragma("unroll") \
            for (int mi = 0; mi < 2; mi++) \
                ldsm4(ah[mi], base + (arow + mi * 16) * 80 + acol); \
            _Pragma("unroll") \
            for (int nf = 0; nf < 4; nf++) { \
                uint32_t bd = base + PLN + (brow + nf * 16) * 80 + bcol; \
                uint32_t bh[4]; \
                ldsm4(bh, bd); \
                mmaf16(acc[0][2*nf],   ah[0], bh[0], bh[1]); \
                mmaf16(acc[0][2*nf+1], ah[0], bh[2], bh[3]); \
                mmaf16(acc[1][2*nf],   ah[1], bh[0], bh[1]); \
                mmaf16(acc[1][2*nf+1], ah[1], bh[2], bh[3]); \
            } \
        } \
        __syncthreads(); \
    } \
} while (0)

#define G2ISSUE(c, s) do { \
    uint32_t d = dst0 + (s) * STG2; int go = (c) * 64; \
    cpa16(d,         pAh + go); cpa16(d + 16,         pAh + go + 16); \
    cpa16(d + PLN,   pAl + go); cpa16(d + PLN + 16,   pAl + go + 16); \
    cpa16(d + 2*PLN, pW  + go); cpa16(d + 2*PLN + 16, pW  + go + 16); \
    asm volatile("cp.async.commit_group;" ::: "memory"); \
} while (0)

#define GEMM2_CORE(gAh, gAl, gW, acc) do { \
    const int crow = t >> 1, coff = (t & 1) * 32; \
    const char* pAh = (const char*)((gAh) + (size_t)(bm + crow) * D_) + coff; \
    const char* pAl = (const char*)((gAl) + (size_t)(bm + crow) * D_) + coff; \
    const char* pW  = (const char*)((gW)  + (size_t)(bn + crow) * D_) + coff; \
    const uint32_t dst0 = sb + crow * 80 + coff; \
    const int NCH = D_ / 32; \
    G2ISSUE(0, 0); G2ISSUE(1, 1); \
    for (int c = 0; c < NCH; c++) { \
        const int s = c % 3; \
        if (c + 2 < NCH) { G2ISSUE(c + 2, (c + 2) % 3); \
            asm volatile("cp.async.wait_group 2;" ::: "memory"); } \
        else if (c + 1 < NCH) { asm volatile("cp.async.wait_group 1;" ::: "memory"); } \
        else { asm volatile("cp.async.wait_group 0;" ::: "memory"); } \
        __syncthreads(); \
        const uint32_t base = sb + s * STG2; \
        const int arow = mw + (lane & 15); \
        const int brow = nw + (lane & 7) + ((lane >> 4) << 3); \
        _Pragma("unroll") \
        for (int ks = 0; ks < 2; ks++) { \
            const int acol = ks * 32 + ((lane >> 4) << 4); \
            const int bcol = ks * 32 + (((lane >> 3) & 1) << 4); \
            uint32_t ah[2][4], al[2][4]; \
            _Pragma("unroll") \
            for (int mi = 0; mi < 2; mi++) { \
                uint32_t ad = base + (arow + mi * 16) * 80 + acol; \
                ldsm4(ah[mi], ad); ldsm4(al[mi], ad + PLN); \
            } \
            _Pragma("unroll") \
            for (int nf = 0; nf < 4; nf++) { \
                uint32_t bd = base + 2 * PLN + (brow + nf * 16) * 80 + bcol; \
                uint32_t bh[4]; \
                ldsm4(bh, bd); \
                mmaf16(acc[0][2*nf],   ah[0], bh[0], bh[1]); \
                mmaf16(acc[0][2*nf+1], ah[0], bh[2], bh[3]); \
                mmaf16(acc[1][2*nf],   ah[1], bh[0], bh[1]); \
                mmaf16(acc[1][2*nf+1], ah[1], bh[2], bh[3]); \
                mmaf16(acc[0][2*nf],   al[0], bh[0], bh[1]); \
                mmaf16(acc[0][2*nf+1], al[0], bh[2], bh[3]); \
                mmaf16(acc[1][2*nf],   al[1], bh[0], bh[1]); \
                mmaf16(acc[1][2*nf+1], al[1], bh[2], bh[3]); \
            } \
        } \
        __syncthreads(); \
    } \
} while (0)

// z-batched QKV projection, 1-term A: z=0 -> Q hi/lo (scaled), z=1 -> K, z=2 -> V fp32
__global__ void __launch_bounds__(256, 2)
gemm_qkv(const __half* __restrict__ Ah3, const __half* __restrict__ Wh4,
         const float* __restrict__ bq, const float* __restrict__ bk,
         const float* __restrict__ bv, float* __restrict__ Vout,
         __half* __restrict__ Qh, __half* __restrict__ Ql,
         __half* __restrict__ Kh, float qsc)
{
    extern __shared__ __align__(128) char sm[];
    const uint32_t sb = smem_u32(sm);
    const int t = threadIdx.x, lane = t & 31, w = t >> 5;
    const int bm = blockIdx.y * 128, bn = blockIdx.x * 128;
    const int mw = (w >> 1) * 32, nw = (w & 1) * 64;
    const int z = blockIdx.z;
    const __half* A = Ah3 + (size_t)z * NACT;
    const __half* W = Wh4 + (size_t)z * D_ * D_;
    const float* bias = (z == 0) ? bq : (z == 1) ? bk : bv;

    float acc[2][8][4] = {};
    GEMM1_CORE(A, W, acc);

    const float osc = (z == 0) ? qsc : 1.0f;
    #pragma unroll
    for (int mi = 0; mi < 2; mi++) {
        const int r0 = bm + mw + mi * 16 + (lane >> 2);
        #pragma unroll
        for (int nj = 0; nj < 8; nj++) {
            const int col = bn + nw + nj * 8 + (lane & 3) * 2;
            float2 bv2 = *(const float2*)&bias[col];
            float* c = acc[mi][nj];
            float v0 = (c[0] + bv2.x) * osc, v1 = (c[1] + bv2.y) * osc;
            float v2 = (c[2] + bv2.x) * osc, v3 = (c[3] + bv2.y) * osc;
            if (z == 2) {
                *(float2*)&Vout[(size_t)r0 * D_ + col] = make_float2(v0, v1);
                *(float2*)&Vout[(size_t)(r0 + 8) * D_ + col] = make_float2(v2, v3);
            } else if (z == 1) {
                *(uint32_t*)&Kh[(size_t)r0 * D_ + col]       = pkh2(v0, v1);
                *(uint32_t*)&Kh[(size_t)(r0 + 8) * D_ + col] = pkh2(v2, v3);
            } else {
                *(uint32_t*)&Qh[(size_t)r0 * D_ + col]       = pkh2(v0, v1);
                *(uint32_t*)&Ql[(size_t)r0 * D_ + col]       = pkh2(hlo(v0), hlo(v1));
                *(uint32_t*)&Qh[(size_t)(r0 + 8) * D_ + col] = pkh2(v2, v3);
                *(uint32_t*)&Ql[(size_t)(r0 + 8) * D_ + col] = pkh2(hlo(v2), hlo(v3));
            }
        }
    }
}

// O projection: 2-term A (ctx hi/lo), fp32 out
__global__ void __launch_bounds__(256, 2)
gemm_o(const __half* __restrict__ Ah, const __half* __restrict__ Al,
       const __half* __restrict__ W, const float* __restrict__ bias,
       float* __restrict__ outf)
{
    extern __shared__ __align__(128) char sm[];
    const uint32_t sb = smem_u32(sm);
    const int t = threadIdx.x, lane = t & 31, w = t >> 5;
    const int bm = blockIdx.y * 128, bn = blockIdx.x * 128;
    const int mw = (w >> 1) * 32, nw = (w & 1) * 64;

    float acc[2][8][4] = {};
    GEMM2_CORE(Ah, Al, W, acc);

    #pragma unroll
    for (int mi = 0; mi < 2; mi++) {
        const int r0 = bm + mw + mi * 16 + (lane >> 2);
        #pragma unroll
        for (int nj = 0; nj < 8; nj++) {
            const int col = bn + nw + nj * 8 + (lane & 3) * 2;
            float2 bv2 = *(const float2*)&bias[col];
            float* c = acc[mi][nj];
            *(float2*)&outf[(size_t)r0 * D_ + col] = make_float2(c[0] + bv2.x, c[1] + bv2.y);
            *(float2*)&outf[(size_t)(r0 + 8) * D_ + col] = make_float2(c[2] + bv2.x, c[3] + bv2.y);
        }
    }
}

// ---------------------------------------------------------------------------
// fp16 flash attention (round-14, passing): QK^T 2-term, PV 1-term,
// exp2 softmax, bitmask, 3-stage K/V ring, fp16 hi/lo ctx output.
// ---------------------------------------------------------------------------
static constexpr int KST   = 144;
static constexpr int KPL   = 64 * KST;
static constexpr int ASTG2 = 2 * KPL;
static constexpr int ASM   = 3 * ASTG2;
static constexpr int QLO   = 128 * KST;

__global__ void __launch_bounds__(128, 2)
attn_mma(const __half* __restrict__ Qh, const __half* __restrict__ Ql,
         const __half* __restrict__ Kh, const __half* __restrict__ Vt,
         const uint32_t* __restrict__ mb,
         __half* __restrict__ ctxh, __half* __restrict__ ctxl)
{
    extern __shared__ __align__(128) char sm[];
    const uint32_t sb = smem_u32(sm);
    const int t = threadIdx.x, lane = t & 31, w = t >> 5;
    const int b = blockIdx.z, h = blockIdx.y, q0 = blockIdx.x * 128;
    const int g = lane >> 2, qt = lane & 3;

    {
        const char* ph = (const char*)(Qh + ((size_t)(b*S_ + q0 + t))*D_ + h*64);
        const char* pl = (const char*)(Ql + ((size_t)(b*S_ + q0 + t))*D_ + h*64);
        uint32_t d = sb + t * KST;
        #pragma unroll
        for (int i = 0; i < 8; i++) { cpa16(d + i*16, ph + i*16); cpa16(d + QLO + i*16, pl + i*16); }
        asm volatile("cp.async.commit_group;" ::: "memory");
        asm volatile("cp.async.wait_group 0;" ::: "memory");
    }
    __syncthreads();
    uint32_t qfh[2][4][4], qfl[2][4][4];
    #pragma unroll
    for (int mi = 0; mi < 2; mi++)
        #pragma unroll
        for (int kc = 0; kc < 4; kc++) {
            uint32_t a = sb + (w*32 + mi*16 + (lane & 15)) * KST + kc*32 + ((lane >> 4) << 4);
            ldsm4(qfh[mi][kc], a);
            ldsm4(qfl[mi][kc], a + QLO);
        }
    __syncthreads();

    float o[2][8][4] = {};
    float m_i[2][2], l_i[2][2];
    #pragma unroll
    for (int mi = 0; mi < 2; mi++) { m_i[mi][0]=m_i[mi][1]=-1e30f; l_i[mi][0]=l_i[mi][1]=0.f; }

    const int krow = t >> 1, khalf = (t & 1) * 64;
    #define AISSUE(c, s) do { \
        uint32_t dd = sb + (s)*ASTG2 + krow*KST + khalf; \
        const char* pkh = (const char*)(Kh + ((size_t)(b*S_ + (c)*64 + krow))*D_ + h*64) + khalf; \
        const char* pvh = (const char*)(Vt + ((size_t)((b*H_+h)*64 + krow))*S_ + (c)*64) + khalf; \
        _Pragma("unroll") for (int i = 0; i < 4; i++) { \
            cpa16(dd + i*16,       pkh + i*16); \
            cpa16(dd + KPL + i*16, pvh + i*16); } \
        asm volatile("cp.async.commit_group;" ::: "memory"); \
    } while (0)

    const int NT = S_ / 64;
    AISSUE(0, 0); AISSUE(1, 1);
    for (int c = 0; c < NT; c++) {
        const int s = c % 3;
        if (c + 2 < NT) { AISSUE(c + 2, (c + 2) % 3);
            asm volatile("cp.async.wait_group 2;" ::: "memory"); }
        else if (c + 1 < NT) { asm volatile("cp.async.wait_group 1;" ::: "memory"); }
        else { asm volatile("cp.async.wait_group 0;" ::: "memory"); }
        __syncthreads();
        const uint32_t base = sb + s * ASTG2;
        const int brow = (lane & 7) + ((lane >> 4) << 3);
        const int bcsel = ((lane >> 3) & 1) << 4;

        uint2 mwa[2], mwb[2];
        #pragma unroll
        for (int mi = 0; mi < 2; mi++) {
            const uint32_t* mp = mb + (size_t)(q0 + w*32 + mi*16 + g) * (S_/32) + c*2;
            mwa[mi] = *(const uint2*)mp;
            mwb[mi] = *(const uint2*)(mp + 8 * (S_/32));
        }

        float sacc[2][8][4] = {};
        #pragma unroll
        for (int kc = 0; kc < 4; kc++)
            #pragma unroll
            for (int np = 0; np < 4; np++) {
                uint32_t ad = base + (np*16 + brow) * KST + kc*32 + bcsel;
                uint32_t kf[4];
                ldsm4(kf, ad);
                mmaf16(sacc[0][2*np],   qfh[0][kc], kf[0], kf[1]);
                mmaf16(sacc[0][2*np+1], qfh[0][kc], kf[2], kf[3]);
                mmaf16(sacc[1][2*np],   qfh[1][kc], kf[0], kf[1]);
                mmaf16(sacc[1][2*np+1], qfh[1][kc], kf[2], kf[3]);
                mmaf16(sacc[0][2*np],   qfl[0][kc], kf[0], kf[1]);
                mmaf16(sacc[0][2*np+1], qfl[0][kc], kf[2], kf[3]);
                mmaf16(sacc[1][2*np],   qfl[1][kc], kf[0], kf[1]);
                mmaf16(sacc[1][2*np+1], qfl[1][kc], kf[2], kf[3]);
            }

        #pragma unroll
        for (int mi = 0; mi < 2; mi++) {
            uint32_t allm = mwa[mi].x & mwa[mi].y & mwb[mi].x & mwb[mi].y;
            if (allm != 0xFFFFFFFFu) {
                #pragma unroll
                for (int nf = 0; nf < 8; nf++) {
                    uint32_t w0 = (nf < 4) ? mwa[mi].x : mwa[mi].y;
                    uint32_t w1 = (nf < 4) ? mwb[mi].x : mwb[mi].y;
                    int sh = qt*2 + (nf & 3)*8;
                    if (!((w0 >> sh) & 1))     sacc[mi][nf][0] = -1e9f;
                    if (!((w0 >> (sh+1)) & 1)) sacc[mi][nf][1] = -1e9f;
                    if (!((w1 >> sh) & 1))     sacc[mi][nf][2] = -1e9f;
                    if (!((w1 >> (sh+1)) & 1)) sacc[mi][nf][3] = -1e9f;
                }
            }
            float mx0 = -1e30f, mx1 = -1e30f;
            #pragma unroll
            for (int nf = 0; nf < 8; nf++) {
                mx0 = fmaxf(mx0, fmaxf(sacc[mi][nf][0], sacc[mi][nf][1]));
                mx1 = fmaxf(mx1, fmaxf(sacc[mi][nf][2], sacc[mi][nf][3]));
            }
            mx0 = fmaxf(mx0, __shfl_xor_sync(0xffffffffu, mx0, 1));
            mx0 = fmaxf(mx0, __shfl_xor_sync(0xffffffffu, mx0, 2));
            mx1 = fmaxf(mx1, __shfl_xor_sync(0xffffffffu, mx1, 1));
            mx1 = fmaxf(mx1, __shfl_xor_sync(0xffffffffu, mx1, 2));
            float mn0 = fmaxf(m_i[mi][0], mx0), mn1 = fmaxf(m_i[mi][1], mx1);
            float al0 = ex2(m_i[mi][0] - mn0), al1 = ex2(m_i[mi][1] - mn1);
            float s0 = 0.f, s1 = 0.f;
            #pragma unroll
            for (int nf = 0; nf < 8; nf++) {
                sacc[mi][nf][0] = ex2(sacc[mi][nf][0] - mn0);
                sacc[mi][nf][1] = ex2(sacc[mi][nf][1] - mn0);
                sacc[mi][nf][2] = ex2(sacc[mi][nf][2] - mn1);
                sacc[mi][nf][3] = ex2(sacc[mi][nf][3] - mn1);
                s0 += sacc[mi][nf][0] + sacc[mi][nf][1];
                s1 += sacc[mi][nf][2] + sacc[mi][nf][3];
            }
            s0 += __shfl_xor_sync(0xffffffffu, s0, 1);
            s0 += __shfl_xor_sync(0xffffffffu, s0, 2);
            s1 += __shfl_xor_sync(0xffffffffu, s1, 1);
            s1 += __shfl_xor_sync(0xffffffffu, s1, 2);
            l_i[mi][0] = l_i[mi][0]*al0 + s0; m_i[mi][0] = mn0;
            l_i[mi][1] = l_i[mi][1]*al1 + s1; m_i[mi][1] = mn1;
            #pragma unroll
            for (int nf = 0; nf < 8; nf++) {
                o[mi][nf][0] *= al0; o[mi][nf][1] *= al0;
                o[mi][nf][2] *= al1; o[mi][nf][3] *= al1;
            }
        }

        #pragma unroll
        for (int kc = 0; kc < 4; kc++) {
            uint32_t ph[2][4];
            #pragma unroll
            for (int mi = 0; mi < 2; mi++) {
                float* c0 = sacc[mi][2*kc];
                float* c1 = sacc[mi][2*kc+1];
                ph[mi][0] = pkh2(c0[0], c0[1]); ph[mi][1] = pkh2(c0[2], c0[3]);
                ph[mi][2] = pkh2(c1[0], c1[1]); ph[mi][3] = pkh2(c1[2], c1[3]);
            }
            #pragma unroll
            for (int np = 0; np < 4; np++) {
                uint32_t vd = base + KPL + (np*16 + brow) * KST + kc*32 + bcsel;
                uint32_t vh[4];
                ldsm4(vh, vd);
                mmaf16(o[0][2*np],   ph[0], vh[0], vh[1]);
                mmaf16(o[0][2*np+1], ph[0], vh[2], vh[3]);
                mmaf16(o[1][2*np],   ph[1], vh[0], vh[1]);
                mmaf16(o[1][2*np+1], ph[1], vh[2], vh[3]);
            }
        }
        __syncthreads();
    }
    #undef AISSUE

    #pragma unroll
    for (int mi = 0; mi < 2; mi++) {
        const int r0 = q0 + w*32 + mi*16 + g;
        const float i0 = 1.f / l_i[mi][0], i1 = 1.f / l_i[mi][1];
        #pragma unroll
        for (int nf = 0; nf < 8; nf++) {
            const int col = h*64 + nf*8 + qt*2;
            float v0 = o[mi][nf][0]*i0, v1 = o[mi][nf][1]*i0;
            float v2 = o[mi][nf][2]*i1, v3 = o[mi][nf][3]*i1;
            *(uint32_t*)&ctxh[(size_t)(b*S_ + r0)*D_ + col]     = pkh2(v0, v1);
            *(uint32_t*)&ctxl[(size_t)(b*S_ + r0)*D_ + col]     = pkh2(hlo(v0), hlo(v1));
            *(uint32_t*)&ctxh[(size_t)(b*S_ + r0 + 8)*D_ + col] = pkh2(v2, v3);
            *(uint32_t*)&ctxl[(size_t)(b*S_ + r0 + 8)*D_ + col] = pkh2(hlo(v2), hlo(v3));
        }
    }
}

// ---------------------------------------------------------------------------
extern "C" void kernel_launch(void* const* d_in, const int* in_sizes, int n_in,
                              void* d_out, int out_size)
{
    const float* q  = (const float*)d_in[0];
    const float* k  = (const float*)d_in[1];
    const float* v  = (const float*)d_in[2];
    const int* mask = (const int*)  d_in[3];
    const float* Wq = (const float*)d_in[4];  const float* bq = (const float*)d_in[5];
    const float* Wk = (const float*)d_in[6];  const float* bk = (const float*)d_in[7];
    const float* Wv = (const float*)d_in[8];  const float* bv = (const float*)d_in[9];
    const float* Wo = (const float*)d_in[10]; const float* bo = (const float*)d_in[11];
    float* out = (float*)d_out;

    float *Vp;
    __half *Ahp, *Alp, *Whp, *Qhp, *Qlp, *Khp, *Vtp;
    uint32_t* mbp;
    cudaGetSymbolAddress((void**)&Vp, g_V);
    cudaGetSymbolAddress((void**)&Ahp, g_Ah); cudaGetSymbolAddress((void**)&Alp, g_Al);
    cudaGetSymbolAddress((void**)&Whp, g_Wh);
    cudaGetSymbolAddress((void**)&Qhp, g_Qh); cudaGetSymbolAddress((void**)&Qlp, g_Ql);
    cudaGetSymbolAddress((void**)&Khp, g_Kh);
    cudaGetSymbolAddress((void**)&Vtp, g_Vt);
    cudaGetSymbolAddress((void**)&mbp, g_mb);

    const int MA4 = NACT / 4 / 256;
    const int MW4 = (D_ * D_) / 4 / 256;
    const float QSC = 0.125f * 1.44269504088896f;

    cudaFuncSetAttribute(gemm_qkv, cudaFuncAttributeMaxDynamicSharedMemorySize, GSM1);
    cudaFuncSetAttribute(gemm_o,   cudaFuncAttributeMaxDynamicSharedMemorySize, GSM2);
    cudaFuncSetAttribute(attn_mma, cudaFuncAttributeMaxDynamicSharedMemorySize, ASM);

    maskbits_kernel<<<(S_*S_)/256, 256>>>(mask, mbp);
    cvt3h_kernel<<<dim3(MA4, 3), 256>>>(q, k, v, Ahp, NACT / 4);
    cvtw_kernel<<<dim3(MW4, 4), 256>>>(Wq, Wk, Wv, Wo, Whp, (D_ * D_) / 4);

    gemm_qkv<<<dim3(D_/128, (B_*S_)/128, 3), 256, GSM1>>>(
        Ahp, Whp, bq, bk, bv, Vp, Qhp, Qlp, Khp, QSC);

    cvtT_kernel<<<dim3(S_/32, D_/32, B_), 256>>>(Vp, Vtp);

    // attn writes ctx hi -> g_Ah slot 0, ctx lo -> g_Al
    attn_mma<<<dim3(S_/128, H_, B_), 128, ASM>>>(Qhp, Qlp, Khp, Vtp, mbp, Ahp, Alp);

    gemm_o<<<dim3(D_/128, (B_*S_)/128), 256, GSM2>>>(
        Ahp, Alp, Whp + (size_t)3*D_*D_, bo, out);
}

// round 17
// speedup vs baseline: 1.3301x; 1.0930x over previous
#include <cuda_runtime.h>
#include <cuda_bf16.h>
#include <cuda_fp16.h>
#include <cstdint>
#define B_ 2
#define S_ 2048
#define D_ 1024
#define H_ 16
#define NACT (B_*S_*D_)

__device__ float g_V[NACT];                         // fp32 V projection
__device__ __half g_Ah[3*NACT], g_Al[NACT];         // act fp16: 3 hi slots; 1 lo slot (ctx)
__device__ __half g_Wh[4*D_*D_];                    // weights single fp16 plane
__device__ __half g_Qh[NACT];                       // attn Q plane (scaled, 1-term)
__device__ __half g_Kh[NACT];                       // attn K plane
__device__ __half g_Vt[NACT];                       // V^T fp16 [b][h][d][s]
__device__ uint32_t g_mb[S_*S_/32];                 // mask bitplane

__device__ __forceinline__ uint32_t smem_u32(const void* p){
    uint32_t a; asm("{ .reg .u64 t; cvta.to.shared.u64 t, %1; cvt.u32.u64 %0, t; }":"=r"(a):"l"(p)); return a;
}
__device__ __forceinline__ void ldsm4(uint32_t* r, uint32_t a){
    asm volatile("ldmatrix.sync.aligned.m8n8.x4.shared.b16 {%0,%1,%2,%3}, [%4];"
        :"=r"(r[0]),"=r"(r[1]),"=r"(r[2]),"=r"(r[3]):"r"(a));
}
__device__ __forceinline__ void mmaf16(float* c, const uint32_t* a, uint32_t b0, uint32_t b1){
    asm("mma.sync.aligned.m16n8k16.row.col.f32.f16.f16.f32 "
        "{%0,%1,%2,%3}, {%4,%5,%6,%7}, {%8,%9}, {%0,%1,%2,%3};"
        :"+f"(c[0]),"+f"(c[1]),"+f"(c[2]),"+f"(c[3])
        :"r"(a[0]),"r"(a[1]),"r"(a[2]),"r"(a[3]),"r"(b0),"r"(b1));
}
__device__ __forceinline__ void cpa16(uint32_t d, const void* s){
    asm volatile("cp.async.cg.shared.global [%0], [%1], 16;"::"r"(d),"l"(s):"memory");
}
__device__ __forceinline__ uint32_t pkh2(float a, float b){
    __half2 h = __floats2half2_rn(a, b);
    return *reinterpret_cast<uint32_t*>(&h);
}
__device__ __forceinline__ float hlo(float v){
    return v - __half2float(__float2half_rn(v));
}
__device__ __forceinline__ float ex2(float x){
    float r; asm("ex2.approx.ftz.f32 %0, %1;":"=f"(r):"f"(x)); return r;
}

// ---------------- mask -> bitplane ----------------
__global__ void __launch_bounds__(256)
maskbits_kernel(const int* __restrict__ mask, uint32_t* __restrict__ bits)
{
    int i = blockIdx.x * 256 + threadIdx.x;
    uint32_t b = __ballot_sync(0xffffffffu, mask[i] != 0);
    if ((threadIdx.x & 31) == 0) bits[i >> 5] = b;
}

// ---------------- z-batched fp32 -> fp16 single plane ----------------
__global__ void __launch_bounds__(256)
cvt3h_kernel(const float* __restrict__ i0, const float* __restrict__ i1,
             const float* __restrict__ i2, __half* __restrict__ hi, int slot_u2)
{
    int z = blockIdx.y;
    const float* in = (z == 0) ? i0 : (z == 1) ? i1 : i2;
    int i = blockIdx.x * 256 + threadIdx.x;
    float4 v = ((const float4*)in)[i];
    unsigned short h[4] = {
        __half_as_ushort(__float2half_rn(v.x)), __half_as_ushort(__float2half_rn(v.y)),
        __half_as_ushort(__float2half_rn(v.z)), __half_as_ushort(__float2half_rn(v.w))};
    ((uint2*)hi)[(size_t)z * slot_u2 + i] =
        make_uint2(h[0]|((uint32_t)h[1]<<16), h[2]|((uint32_t)h[3]<<16));
}
__global__ void __launch_bounds__(256)
cvtw_kernel(const float* __restrict__ i0, const float* __restrict__ i1,
            const float* __restrict__ i2, const float* __restrict__ i3,
            __half* __restrict__ hi, int slot_u2)
{
    int z = blockIdx.y;
    const float* in = (z == 0) ? i0 : (z == 1) ? i1 : (z == 2) ? i2 : i3;
    int i = blockIdx.x * 256 + threadIdx.x;
    float4 v = ((const float4*)in)[i];
    unsigned short h[4] = {
        __half_as_ushort(__float2half_rn(v.x)), __half_as_ushort(__float2half_rn(v.y)),
        __half_as_ushort(__float2half_rn(v.z)), __half_as_ushort(__float2half_rn(v.w))};
    ((uint2*)hi)[(size_t)z * slot_u2 + i] =
        make_uint2(h[0]|((uint32_t)h[1]<<16), h[2]|((uint32_t)h[3]<<16));
}
// V[b][s][h*64+d] -> Vt[b][h][d][s] fp16
__global__ void __launch_bounds__(256)
cvtT_kernel(const float* __restrict__ V, __half* __restrict__ oh)
{
    __shared__ float tile[32][33];
    const int s0 = blockIdx.x*32, d0 = blockIdx.y*32, b = blockIdx.z;
    const int tx = threadIdx.x & 31, ty = threadIdx.x >> 5;
    #pragma unroll
    for (int i = 0; i < 4; i++)
        tile[ty+8*i][tx] = V[((size_t)(b*S_+s0+ty+8*i))*D_ + d0+tx];
    __syncthreads();
    const int hh = d0 >> 6, dl = d0 & 63;
    #pragma unroll
    for (int i = 0; i < 4; i++) {
        int dr = ty + 8*i;
        size_t a = ((size_t)((b*H_+hh)*64 + dl + dr))*S_ + s0 + tx;
        oh[a] = __float2half(tile[tx][dr]);
    }
}

// ---------------------------------------------------------------------------
// GEMM cores: 128x128 CTA tile, 8 warps (4Mx2N, warp 32x64), BK=32,
// 3-stage cp.async ring. 1-term (A,W) and 2-term (Ah,Al,W) variants.
// ---------------------------------------------------------------------------
static constexpr int PLN   = 128 * 80;
static constexpr int STG1  = 2 * PLN;
static constexpr int STG2  = 3 * PLN;
static constexpr int GSM1  = 3 * STG1;
static constexpr int GSM2  = 3 * STG2;

#define G1ISSUE(c, s) do { \
    uint32_t d = dst0 + (s) * STG1; int go = (c) * 64; \
    cpa16(d,       pA + go); cpa16(d + 16,       pA + go + 16); \
    cpa16(d + PLN, pW + go); cpa16(d + PLN + 16, pW + go + 16); \
    asm volatile("cp.async.commit_group;" ::: "memory"); \
} while (0)

#define GEMM1_CORE(gA, gW, acc) do { \
    const int crow = t >> 1, coff = (t & 1) * 32; \
    const char* pA = (const char*)((gA) + (size_t)(bm + crow) * D_) + coff; \
    const char* pW = (const char*)((gW) + (size_t)(bn + crow) * D_) + coff; \
    const uint32_t dst0 = sb + crow * 80 + coff; \
    const int NCH = D_ / 32; \
    G1ISSUE(0, 0); G1ISSUE(1, 1); \
    for (int c = 0; c < NCH; c++) { \
        const int s = c % 3; \
        if (c + 2 < NCH) { G1ISSUE(c + 2, (c + 2) % 3); \
            asm volatile("cp.async.wait_group 2;" ::: "memory"); } \
        else if (c + 1 < NCH) { asm volatile("cp.async.wait_group 1;" ::: "memory"); } \
        else { asm volatile("cp.async.wait_group 0;" ::: "memory"); } \
        __syncthreads(); \
        const uint32_t base = sb + s * STG1; \
        const int arow = mw + (lane & 15); \
        const int brow = nw + (lane & 7) + ((lane >> 4) << 3); \
        _Pragma("unroll") \
        for (int ks = 0; ks < 2; ks++) { \
            const int acol = ks * 32 + ((lane >> 4) << 4); \
            const int bcol = ks * 32 + (((lane >> 3) & 1) << 4); \
            uint32_t ah[2][4]; \
            _Pragma("unroll") \
            for (int mi = 0; mi < 2; mi++) \
                ldsm4(ah[mi], base + (arow + mi * 16) * 80 + acol); \
            _Pragma("unroll") \
            for (int nf = 0; nf < 4; nf++) { \
                uint32_t bd = base + PLN + (brow + nf * 16) * 80 + bcol; \
                uint32_t bh[4]; \
                ldsm4(bh, bd); \
                mmaf16(acc[0][2*nf],   ah[0], bh[0], bh[1]); \
                mmaf16(acc[0][2*nf+1], ah[0], bh[2], bh[3]); \
                mmaf16(acc[1][2*nf],   ah[1], bh[0], bh[1]); \
                mmaf16(acc[1][2*nf+1], ah[1], bh[2], bh[3]); \
            } \
        } \
        __syncthreads(); \
    } \
} while (0)

#define G2ISSUE(c, s) do { \
    uint32_t d = dst0 + (s) * STG2; int go = (c) * 64; \
    cpa16(d,         pAh + go); cpa16(d + 16,         pAh + go + 16); \
    cpa16(d + PLN,   pAl + go); cpa16(d + PLN + 16,   pAl + go + 16); \
    cpa16(d + 2*PLN, pW  + go); cpa16(d + 2*PLN + 16, pW  + go + 16); \
    asm volatile("cp.async.commit_group;" ::: "memory"); \
} while (0)

#define GEMM2_CORE(gAh, gAl, gW, acc) do { \
    const int crow = t >> 1, coff = (t & 1) * 32; \
    const char* pAh = (const char*)((gAh) + (size_t)(bm + crow) * D_) + coff; \
    const char* pAl = (const char*)((gAl) + (size_t)(bm + crow) * D_) + coff; \
    const char* pW  = (const char*)((gW)  + (size_t)(bn + crow) * D_) + coff; \
    const uint32_t dst0 = sb + crow * 80 + coff; \
    const int NCH = D_ / 32; \
    G2ISSUE(0, 0); G2ISSUE(1, 1); \
    for (int c = 0; c < NCH; c++) { \
        const int s = c % 3; \
        if (c + 2 < NCH) { G2ISSUE(c + 2, (c + 2) % 3); \
            asm volatile("cp.async.wait_group 2;" ::: "memory"); } \
        else if (c + 1 < NCH) { asm volatile("cp.async.wait_group 1;" ::: "memory"); } \
        else { asm volatile("cp.async.wait_group 0;" ::: "memory"); } \
        __syncthreads(); \
        const uint32_t base = sb + s * STG2; \
        const int arow = mw + (lane & 15); \
        const int brow = nw + (lane & 7) + ((lane >> 4) << 3); \
        _Pragma("unroll") \
        for (int ks = 0; ks < 2; ks++) { \
            const int acol = ks * 32 + ((lane >> 4) << 4); \
            const int bcol = ks * 32 + (((lane >> 3) & 1) << 4); \
            uint32_t ah[2][4], al[2][4]; \
            _Pragma("unroll") \
            for (int mi = 0; mi < 2; mi++) { \
                uint32_t ad = base + (arow + mi * 16) * 80 + acol; \
                ldsm4(ah[mi], ad); ldsm4(al[mi], ad + PLN); \
            } \
            _Pragma("unroll") \
            for (int nf = 0; nf < 4; nf++) { \
                uint32_t bd = base + 2 * PLN + (brow + nf * 16) * 80 + bcol; \
                uint32_t bh[4]; \
                ldsm4(bh, bd); \
                mmaf16(acc[0][2*nf],   ah[0], bh[0], bh[1]); \
                mmaf16(acc[0][2*nf+1], ah[0], bh[2], bh[3]); \
                mmaf16(acc[1][2*nf],   ah[1], bh[0], bh[1]); \
                mmaf16(acc[1][2*nf+1], ah[1], bh[2], bh[3]); \
                mmaf16(acc[0][2*nf],   al[0], bh[0], bh[1]); \
                mmaf16(acc[0][2*nf+1], al[0], bh[2], bh[3]); \
                mmaf16(acc[1][2*nf],   al[1], bh[0], bh[1]); \
                mmaf16(acc[1][2*nf+1], al[1], bh[2], bh[3]); \
            } \
        } \
        __syncthreads(); \
    } \
} while (0)

// z-batched QKV projection, 1-term A: z=0 -> Q (scaled), z=1 -> K, z=2 -> V fp32
__global__ void __launch_bounds__(256, 2)
gemm_qkv(const __half* __restrict__ Ah3, const __half* __restrict__ Wh4,
         const float* __restrict__ bq, const float* __restrict__ bk,
         const float* __restrict__ bv, float* __restrict__ Vout,
         __half* __restrict__ Qh, __half* __restrict__ Kh, float qsc)
{
    extern __shared__ __align__(128) char sm[];
    const uint32_t sb = smem_u32(sm);
    const int t = threadIdx.x, lane = t & 31, w = t >> 5;
    const int bm = blockIdx.y * 128, bn = blockIdx.x * 128;
    const int mw = (w >> 1) * 32, nw = (w & 1) * 64;
    const int z = blockIdx.z;
    const __half* A = Ah3 + (size_t)z * NACT;
    const __half* W = Wh4 + (size_t)z * D_ * D_;
    const float* bias = (z == 0) ? bq : (z == 1) ? bk : bv;

    float acc[2][8][4] = {};
    GEMM1_CORE(A, W, acc);

    const float osc = (z == 0) ? qsc : 1.0f;
    #pragma unroll
    for (int mi = 0; mi < 2; mi++) {
        const int r0 = bm + mw + mi * 16 + (lane >> 2);
        #pragma unroll
        for (int nj = 0; nj < 8; nj++) {
            const int col = bn + nw + nj * 8 + (lane & 3) * 2;
            float2 bv2 = *(const float2*)&bias[col];
            float* c = acc[mi][nj];
            float v0 = (c[0] + bv2.x) * osc, v1 = (c[1] + bv2.y) * osc;
            float v2 = (c[2] + bv2.x) * osc, v3 = (c[3] + bv2.y) * osc;
            if (z == 2) {
                *(float2*)&Vout[(size_t)r0 * D_ + col] = make_float2(v0, v1);
                *(float2*)&Vout[(size_t)(r0 + 8) * D_ + col] = make_float2(v2, v3);
            } else {
                __half* dst = (z == 0) ? Qh : Kh;
                *(uint32_t*)&dst[(size_t)r0 * D_ + col]       = pkh2(v0, v1);
                *(uint32_t*)&dst[(size_t)(r0 + 8) * D_ + col] = pkh2(v2, v3);
            }
        }
    }
}

// O projection: 2-term A (ctx hi/lo), fp32 out
__global__ void __launch_bounds__(256, 2)
gemm_o(const __half* __restrict__ Ah, const __half* __restrict__ Al,
       const __half* __restrict__ W, const float* __restrict__ bias,
       float* __restrict__ outf)
{
    extern __shared__ __align__(128) char sm[];
    const uint32_t sb = smem_u32(sm);
    const int t = threadIdx.x, lane = t & 31, w = t >> 5;
    const int bm = blockIdx.y * 128, bn = blockIdx.x * 128;
    const int mw = (w >> 1) * 32, nw = (w & 1) * 64;

    float acc[2][8][4] = {};
    GEMM2_CORE(Ah, Al, W, acc);

    #pragma unroll
    for (int mi = 0; mi < 2; mi++) {
        const int r0 = bm + mw + mi * 16 + (lane >> 2);
        #pragma unroll
        for (int nj = 0; nj < 8; nj++) {
            const int col = bn + nw + nj * 8 + (lane & 3) * 2;
            float2 bv2 = *(const float2*)&bias[col];
            float* c = acc[mi][nj];
            *(float2*)&outf[(size_t)r0 * D_ + col] = make_float2(c[0] + bv2.x, c[1] + bv2.y);
            *(float2*)&outf[(size_t)(r0 + 8) * D_ + col] = make_float2(c[2] + bv2.x, c[3] + bv2.y);
        }
    }
}

// ---------------------------------------------------------------------------
// fp16 flash attention: QK^T 1-term, PV 1-term, exp2 softmax, bitmask,
// 3-stage K/V ring, fp16 hi/lo ctx output.
// ---------------------------------------------------------------------------
static constexpr int KST   = 144;
static constexpr int KPL   = 64 * KST;
static constexpr int ASTG2 = 2 * KPL;
static constexpr int ASM   = 3 * ASTG2;

__global__ void __launch_bounds__(128, 2)
attn_mma(const __half* __restrict__ Qh, const __half* __restrict__ Kh,
         const __half* __restrict__ Vt, const uint32_t* __restrict__ mb,
         __half* __restrict__ ctxh, __half* __restrict__ ctxl)
{
    extern __shared__ __align__(128) char sm[];
    const uint32_t sb = smem_u32(sm);
    const int t = threadIdx.x, lane = t & 31, w = t >> 5;
    const int b = blockIdx.z, h = blockIdx.y, q0 = blockIdx.x * 128;
    const int g = lane >> 2, qt = lane & 3;

    {   // stage Q tile (single plane), extract persistent A-frags
        const char* ph = (const char*)(Qh + ((size_t)(b*S_ + q0 + t))*D_ + h*64);
        uint32_t d = sb + t * KST;
        #pragma unroll
        for (int i = 0; i < 8; i++) cpa16(d + i*16, ph + i*16);
        asm volatile("cp.async.commit_group;" ::: "memory");
        asm volatile("cp.async.wait_group 0;" ::: "memory");
    }
    __syncthreads();
    uint32_t qf[2][4][4];
    #pragma unroll
    for (int mi = 0; mi < 2; mi++)
        #pragma unroll
        for (int kc = 0; kc < 4; kc++)
            ldsm4(qf[mi][kc],
                  sb + (w*32 + mi*16 + (lane & 15)) * KST + kc*32 + ((lane >> 4) << 4));
    __syncthreads();

    float o[2][8][4] = {};
    float m_i[2][2], l_i[2][2];
    #pragma unroll
    for (int mi = 0; mi < 2; mi++) { m_i[mi][0]=m_i[mi][1]=-1e30f; l_i[mi][0]=l_i[mi][1]=0.f; }

    const int krow = t >> 1, khalf = (t & 1) * 64;
    #define AISSUE(c, s) do { \
        uint32_t dd = sb + (s)*ASTG2 + krow*KST + khalf; \
        const char* pkh = (const char*)(Kh + ((size_t)(b*S_ + (c)*64 + krow))*D_ + h*64) + khalf; \
        const char* pvh = (const char*)(Vt + ((size_t)((b*H_+h)*64 + krow))*S_ + (c)*64) + khalf; \
        _Pragma("unroll") for (int i = 0; i < 4; i++) { \
            cpa16(dd + i*16,       pkh + i*16); \
            cpa16(dd + KPL + i*16, pvh + i*16); } \
        asm volatile("cp.async.commit_group;" ::: "memory"); \
    } while (0)

    const int NT = S_ / 64;
    AISSUE(0, 0); AISSUE(1, 1);
    for (int c = 0; c < NT; c++) {
        const int s = c % 3;
        if (c + 2 < NT) { AISSUE(c + 2, (c + 2) % 3);
            asm volatile("cp.async.wait_group 2;" ::: "memory"); }
        else if (c + 1 < NT) { asm volatile("cp.async.wait_group 1;" ::: "memory"); }
        else { asm volatile("cp.async.wait_group 0;" ::: "memory"); }
        __syncthreads();
        const uint32_t base = sb + s * ASTG2;
        const int brow = (lane & 7) + ((lane >> 4) << 3);
        const int bcsel = ((lane >> 3) & 1) << 4;

        uint2 mwa[2], mwb[2];
        #pragma unroll
        for (int mi = 0; mi < 2; mi++) {
            const uint32_t* mp = mb + (size_t)(q0 + w*32 + mi*16 + g) * (S_/32) + c*2;
            mwa[mi] = *(const uint2*)mp;
            mwb[mi] = *(const uint2*)(mp + 8 * (S_/32));
        }

        // ---- S = Q K^T (fp16, 1 term) ----
        float sacc[2][8][4] = {};
        #pragma unroll
        for (int kc = 0; kc < 4; kc++)
            #pragma unroll
            for (int np = 0; np < 4; np++) {
                uint32_t ad = base + (np*16 + brow) * KST + kc*32 + bcsel;
                uint32_t kf[4];
                ldsm4(kf, ad);
                mmaf16(sacc[0][2*np],   qf[0][kc], kf[0], kf[1]);
                mmaf16(sacc[0][2*np+1], qf[0][kc], kf[2], kf[3]);
                mmaf16(sacc[1][2*np],   qf[1][kc], kf[0], kf[1]);
                mmaf16(sacc[1][2*np+1], qf[1][kc], kf[2], kf[3]);
            }

        // ---- mask + online softmax (exp2 domain) ----
        #pragma unroll
        for (int mi = 0; mi < 2; mi++) {
            uint32_t allm = mwa[mi].x & mwa[mi].y & mwb[mi].x & mwb[mi].y;
            if (allm != 0xFFFFFFFFu) {
                #pragma unroll
                for (int nf = 0; nf < 8; nf++) {
                    uint32_t w0 = (nf < 4) ? mwa[mi].x : mwa[mi].y;
                    uint32_t w1 = (nf < 4) ? mwb[mi].x : mwb[mi].y;
                    int sh = qt*2 + (nf & 3)*8;
                    if (!((w0 >> sh) & 1))     sacc[mi][nf][0] = -1e9f;
                    if (!((w0 >> (sh+1)) & 1)) sacc[mi][nf][1] = -1e9f;
                    if (!((w1 >> sh) & 1))     sacc[mi][nf][2] = -1e9f;
                    if (!((w1 >> (sh+1)) & 1)) sacc[mi][nf][3] = -1e9f;
                }
            }
            float mx0 = -1e30f, mx1 = -1e30f;
            #pragma unroll
            for (int nf = 0; nf < 8; nf++) {
                mx0 = fmaxf(mx0, fmaxf(sacc[mi][nf][0], sacc[mi][nf][1]));
                mx1 = fmaxf(mx1, fmaxf(sacc[mi][nf][2], sacc[mi][nf][3]));
            }
            mx0 = fmaxf(mx0, __shfl_xor_sync(0xffffffffu, mx0, 1));
            mx0 = fmaxf(mx0, __shfl_xor_sync(0xffffffffu, mx0, 2));
            mx1 = fmaxf(mx1, __shfl_xor_sync(0xffffffffu, mx1, 1));
            mx1 = fmaxf(mx1, __shfl_xor_sync(0xffffffffu, mx1, 2));
            float mn0 = fmaxf(m_i[mi][0], mx0), mn1 = fmaxf(m_i[mi][1], mx1);
            float al0 = ex2(m_i[mi][0] - mn0), al1 = ex2(m_i[mi][1] - mn1);
            float s0 = 0.f, s1 = 0.f;
            #pragma unroll
            for (int nf = 0; nf < 8; nf++) {
                sacc[mi][nf][0] = ex2(sacc[mi][nf][0] - mn0);
                sacc[mi][nf][1] = ex2(sacc[mi][nf][1] - mn0);
                sacc[mi][nf][2] = ex2(sacc[mi][nf][2] - mn1);
                sacc[mi][nf][3] = ex2(sacc[mi][nf][3] - mn1);
                s0 += sacc[mi][nf][0] + sacc[mi][nf][1];
                s1 += sacc[mi][nf][2] + sacc[mi][nf][3];
            }
            s0 += __shfl_xor_sync(0xffffffffu, s0, 1);
            s0 += __shfl_xor_sync(0xffffffffu, s0, 2);
            s1 += __shfl_xor_sync(0xffffffffu, s1, 1);
            s1 += __shfl_xor_sync(0xffffffffu, s1, 2);
            l_i[mi][0] = l_i[mi][0]*al0 + s0; m_i[mi][0] = mn0;
            l_i[mi][1] = l_i[mi][1]*al1 + s1; m_i[mi][1] = mn1;
            #pragma unroll
            for (int nf = 0; nf < 8; nf++) {
                o[mi][nf][0] *= al0; o[mi][nf][1] *= al0;
                o[mi][nf][2] *= al1; o[mi][nf][3] *= al1;
            }
        }

        // ---- O += P V (fp16 single term) ----
        #pragma unroll
        for (int kc = 0; kc < 4; kc++) {
            uint32_t ph[2][4];
            #pragma unroll
            for (int mi = 0; mi < 2; mi++) {
                float* c0 = sacc[mi][2*kc];
                float* c1 = sacc[mi][2*kc+1];
                ph[mi][0] = pkh2(c0[0], c0[1]); ph[mi][1] = pkh2(c0[2], c0[3]);
                ph[mi][2] = pkh2(c1[0], c1[1]); ph[mi][3] = pkh2(c1[2], c1[3]);
            }
            #pragma unroll
            for (int np = 0; np < 4; np++) {
                uint32_t vd = base + KPL + (np*16 + brow) * KST + kc*32 + bcsel;
                uint32_t vh[4];
                ldsm4(vh, vd);
                mmaf16(o[0][2*np],   ph[0], vh[0], vh[1]);
                mmaf16(o[0][2*np+1], ph[0], vh[2], vh[3]);
                mmaf16(o[1][2*np],   ph[1], vh[0], vh[1]);
                mmaf16(o[1][2*np+1], ph[1], vh[2], vh[3]);
            }
        }
        __syncthreads();
    }
    #undef AISSUE

    #pragma unroll
    for (int mi = 0; mi < 2; mi++) {
        const int r0 = q0 + w*32 + mi*16 + g;
        const float i0 = 1.f / l_i[mi][0], i1 = 1.f / l_i[mi][1];
        #pragma unroll
        for (int nf = 0; nf < 8; nf++) {
            const int col = h*64 + nf*8 + qt*2;
            float v0 = o[mi][nf][0]*i0, v1 = o[mi][nf][1]*i0;
            float v2 = o[mi][nf][2]*i1, v3 = o[mi][nf][3]*i1;
            *(uint32_t*)&ctxh[(size_t)(b*S_ + r0)*D_ + col]     = pkh2(v0, v1);
            *(uint32_t*)&ctxl[(size_t)(b*S_ + r0)*D_ + col]     = pkh2(hlo(v0), hlo(v1));
            *(uint32_t*)&ctxh[(size_t)(b*S_ + r0 + 8)*D_ + col] = pkh2(v2, v3);
            *(uint32_t*)&ctxl[(size_t)(b*S_ + r0 + 8)*D_ + col] = pkh2(hlo(v2), hlo(v3));
        }
    }
}

// ---------------------------------------------------------------------------
extern "C" void kernel_launch(void* const* d_in, const int* in_sizes, int n_in,
                              void* d_out, int out_size)
{
    const float* q  = (const float*)d_in[0];
    const float* k  = (const float*)d_in[1];
    const float* v  = (const float*)d_in[2];
    const int* mask = (const int*)  d_in[3];
    const float* Wq = (const float*)d_in[4];  const float* bq = (const float*)d_in[5];
    const float* Wk = (const float*)d_in[6];  const float* bk = (const float*)d_in[7];
    const float* Wv = (const float*)d_in[8];  const float* bv = (const float*)d_in[9];
    const float* Wo = (const float*)d_in[10]; const float* bo = (const float*)d_in[11];
    float* out = (float*)d_out;

    float *Vp;
    __half *Ahp, *Alp, *Whp, *Qhp, *Khp, *Vtp;
    uint32_t* mbp;
    cudaGetSymbolAddress((void**)&Vp, g_V);
    cudaGetSymbolAddress((void**)&Ahp, g_Ah); cudaGetSymbolAddress((void**)&Alp, g_Al);
    cudaGetSymbolAddress((void**)&Whp, g_Wh);
    cudaGetSymbolAddress((void**)&Qhp, g_Qh);
    cudaGetSymbolAddress((void**)&Khp, g_Kh);
    cudaGetSymbolAddress((void**)&Vtp, g_Vt);
    cudaGetSymbolAddress((void**)&mbp, g_mb);

    const int MA4 = NACT / 4 / 256;
    const int MW4 = (D_ * D_) / 4 / 256;
    const float QSC = 0.125f * 1.44269504088896f;

    cudaFuncSetAttribute(gemm_qkv, cudaFuncAttributeMaxDynamicSharedMemorySize, GSM1);
    cudaFuncSetAttribute(gemm_o,   cudaFuncAttributeMaxDynamicSharedMemorySize, GSM2);
    cudaFuncSetAttribute(attn_mma, cudaFuncAttributeMaxDynamicSharedMemorySize, ASM);

    maskbits_kernel<<<(S_*S_)/256, 256>>>(mask, mbp);
    cvt3h_kernel<<<dim3(MA4, 3), 256>>>(q, k, v, Ahp, NACT / 4);
    cvtw_kernel<<<dim3(MW4, 4), 256>>>(Wq, Wk, Wv, Wo, Whp, (D_ * D_) / 4);

    gemm_qkv<<<dim3(D_/128, (B_*S_)/128, 3), 256, GSM1>>>(
        Ahp, Whp, bq, bk, bv, Vp, Qhp, Khp, QSC);

    cvtT_kernel<<<dim3(S_/32, D_/32, B_), 256>>>(Vp, Vtp);

    // attn writes ctx hi -> g_Ah slot 0, ctx lo -> g_Al
    attn_mma<<<dim3(S_/128, H_, B_), 128, ASM>>>(Qhp, Khp, Vtp, mbp, Ahp, Alp);

    gemm_o<<<dim3(D_/128, (B_*S_)/128), 256, GSM2>>>(
        Ahp, Alp, Whp + (size_t)3*D_*D_, bo, out);
}